// round 13
// baseline (speedup 1.0000x reference)
#include <cuda_runtime.h>
#include <cuda_bf16.h>

#define NB   16
#define DB   128
#define HW   (192 * 256)      // 49152 points per batch
#define BPN  64               // blocks per batch
#define TPB  256
#define PPB  (HW / BPN)       // 768 points per block
#define PPT  (PPB / TPB)      // 3 points per thread

#define INF_BITS 0x7f800000u

// Write-only partials (no init needed; every element written every launch).
__device__ float g_part2[NB * BPN * DB];   // per-(n,block,bin) min |g - b|
__device__ float g_l1p[NB * BPN];          // per-(n,block) loss1 partial sum
__device__ int   g_vcp[NB * BPN];          // per-(n,block) valid count

// Fused pass: stage clamped points in shared; loss1 via binary search on sorted bins,
// loss2 via brute-force scan of the block's points. Mask is INT32 (harness has no bool).
__global__ void __launch_bounds__(TPB) k_main(const float* __restrict__ bins,
                                              const float* __restrict__ tdm,
                                              const int* __restrict__ mask) {
    __shared__ float sb[DB];          // bins for this batch (sorted ascending)
    __shared__ float sg[PPB];         // clamped point values g for this block's tile
    __shared__ float s2[TPB];         // per-(bin,half) loss2 partials
    __shared__ float swl[TPB / 32];
    __shared__ int   swc[TPB / 32];

    const int n   = blockIdx.y;
    const int bx  = blockIdx.x;
    const int tid = threadIdx.x;

    if (tid < DB) sb[tid] = bins[n * DB + tid];
    __syncthreads();

    const float b0   = sb[0];
    const int   base = n * HW + bx * PPB;

    // Stage g = valid ? max(t, b0) : b0   (== max(where(mask,t,0), b0) since b0 > 0)
    float gp[PPT];
    int   vc = 0;
    #pragma unroll
    for (int i = 0; i < PPT; ++i) {
        int   p = tid + i * TPB;
        float t = __ldg(&tdm[base + p]);
        int   m = __ldg(&mask[base + p]) != 0;
        vc += m;
        float g = m ? fmaxf(t, b0) : b0;
        gp[i] = g;
        sg[p] = g;
    }
    __syncthreads();

    // ---- loss1: per point, distance to nearest bin via binary search (bins sorted, g >= b0).
    // Invalid points have g = b0 exactly -> lo = 0, d1 = 0 -> contribute exact 0.
    int lo[PPT], hi[PPT];
    #pragma unroll
    for (int i = 0; i < PPT; ++i) { lo[i] = 0; hi[i] = DB - 1; }

    #pragma unroll
    for (int it = 0; it < 7; ++it) {          // 2^7 = 128 bins
        #pragma unroll
        for (int i = 0; i < PPT; ++i) {       // 3 independent searches -> ILP over LDS latency
            int   mid = (lo[i] + hi[i] + 1) >> 1;
            float bm  = sb[mid];
            bool  le  = (bm <= gp[i]);
            lo[i] = le ? mid : lo[i];
            hi[i] = le ? hi[i] : mid - 1;
        }
    }

    float l1 = 0.0f;
    #pragma unroll
    for (int i = 0; i < PPT; ++i) {
        float d1 = gp[i] - sb[lo[i]];                                        // >= 0
        float d2 = (lo[i] < DB - 1) ? (sb[lo[i] + 1] - gp[i])
                                    : __int_as_float(INF_BITS);
        l1 += fminf(d1, d2);
    }

    // ---- loss2: per (bin, half-of-tile), min over 384 points ----
    const int   bin  = tid & (DB - 1);
    const int   half = tid >> 7;              // 0 or 1
    const float bj   = sb[bin];
    const float4* sg4 = (const float4*)(sg + half * (PPB / 2));

    float n0 = __int_as_float(INF_BITS), n1 = n0;   // 2 independent dependency chains
    #pragma unroll 8
    for (int q = 0; q < (PPB / 2) / 4; ++q) {
        float4 v = sg4[q];            // LDS.128, broadcast (same q, same half across warp)
        n0 = fminf(n0, fabsf(v.x - bj));
        n1 = fminf(n1, fabsf(v.y - bj));
        n0 = fminf(n0, fabsf(v.z - bj));
        n1 = fminf(n1, fabsf(v.w - bj));
    }
    s2[tid] = fminf(n0, n1);

    // ---- reduce loss1 + valid count over the block ----
    #pragma unroll
    for (int o = 16; o; o >>= 1) {
        l1 += __shfl_down_sync(0xffffffffu, l1, o);
        vc += __shfl_down_sync(0xffffffffu, vc, o);
    }
    if ((tid & 31) == 0) { swl[tid >> 5] = l1; swc[tid >> 5] = vc; }
    __syncthreads();

    if (tid == 0) {
        float L = 0.0f; int C = 0;
        #pragma unroll
        for (int w = 0; w < TPB / 32; ++w) { L += swl[w]; C += swc[w]; }
        g_l1p[n * BPN + bx] = L;
        g_vcp[n * BPN + bx] = C;
    }

    // ---- per-bin partial mins: plain coalesced store, no atomics ----
    if (tid < DB) {
        g_part2[(n * BPN + bx) * DB + tid] = fminf(s2[tid], s2[tid + DB]);
    }
}

// One block per batch: reduce 64 partials per bin, sum bins, add loss1, divide by global count.
__global__ void __launch_bounds__(DB) k_final(float* __restrict__ out) {
    __shared__ float redf[DB / 32];
    __shared__ int   redi[DB / 32];
    const int n = blockIdx.x, tid = threadIdx.x;

    // loss2: min over this batch's 64 block-partials for bin 'tid' (coalesced)
    float l2 = __int_as_float(INF_BITS);
    #pragma unroll 8
    for (int b = 0; b < BPN; ++b)
        l2 = fminf(l2, g_part2[(n * BPN + b) * DB + tid]);

    // loss1 partials for this batch: first 64 threads read one each
    float l1 = (tid < BPN) ? g_l1p[n * BPN + tid] : 0.0f;

    // valid count is GLOBAL (sum over all batches): 1024 values, 8 per thread
    int vc = 0;
    #pragma unroll
    for (int i = 0; i < (NB * BPN) / DB; ++i)
        vc += g_vcp[tid + i * DB];

    float acc = l1 + l2;
    #pragma unroll
    for (int o = 16; o; o >>= 1) {
        acc += __shfl_down_sync(0xffffffffu, acc, o);
        vc  += __shfl_down_sync(0xffffffffu, vc,  o);
    }
    if ((tid & 31) == 0) { redf[tid >> 5] = acc; redi[tid >> 5] = vc; }
    __syncthreads();

    if (tid == 0) {
        float s = 0.0f; int c = 0;
        #pragma unroll
        for (int w = 0; w < DB / 32; ++w) { s += redf[w]; c += redi[w]; }
        out[n] = s / (float)c;
    }
}

extern "C" void kernel_launch(void* const* d_in, const int* in_sizes, int n_in,
                              void* d_out, int out_size) {
    const float* bins = (const float*)d_in[0];
    const float* tdm  = (const float*)d_in[1];
    const int*   mask = (const int*)d_in[2];     // jnp.bool_ materialized as int32
    float*       out  = (float*)d_out;

    dim3 grid(BPN, NB);
    k_main<<<grid, TPB>>>(bins, tdm, mask);
    k_final<<<NB, DB>>>(out);
}

// round 16
// speedup vs baseline: 1.4485x; 1.4485x over previous
#include <cuda_runtime.h>
#include <cuda_bf16.h>

#define NB   16
#define DB   128
#define HW   (192 * 256)      // 49152 points per batch
#define BPN  8                // blocks per batch -> 128 blocks total (one wave)
#define TPB  512
#define PPB  (HW / BPN)       // 6144 points per block
#define GPT  (PPB / (TPB * 4))// 3 float4-groups per thread

#define INF_BITS 0x7f800000u

// Write-only partials (no init needed; every element written every launch).
__device__ float g_psmin[NB * BPN * DB];   // per-(n,block,seg) min point value (INF if empty)
__device__ float g_psmax[NB * BPN * DB];   // per-(n,block,seg) max point value (0 if empty)
__device__ float g_l1p[NB * BPN];          // per-(n,block) loss1 partial sum
__device__ int   g_vcp[NB * BPN];          // per-(n,block) valid count

// Per point: binary search on sorted bins -> loss1 term + segment extrema updates.
__global__ void __launch_bounds__(TPB) k_main(const float* __restrict__ bins,
                                              const float* __restrict__ tdm,
                                              const int* __restrict__ mask) {
    __shared__ float    sb[DB];           // sorted bins
    __shared__ unsigned smin[DB], smax[DB];
    __shared__ float    swl[TPB / 32];
    __shared__ int      swc[TPB / 32];
    __shared__ int      s_inv;

    const int n   = blockIdx.y;
    const int bx  = blockIdx.x;
    const int tid = threadIdx.x;

    if (tid < DB) { sb[tid] = bins[n * DB + tid]; smin[tid] = INF_BITS; smax[tid] = 0u; }
    if (tid == 0) s_inv = 0;
    __syncthreads();

    const float b0   = sb[0];
    const int   base = n * HW + bx * PPB;
    const float4* tdm4 = (const float4*)(tdm + base);
    const int4*   msk4 = (const int4*)(mask + base);

    float l1 = 0.0f;
    int   vc = 0, inv = 0;

    #pragma unroll
    for (int i = 0; i < GPT; ++i) {
        int    q = tid + i * TPB;
        float4 t = __ldg(&tdm4[q]);
        int4   m = __ldg(&msk4[q]);

        float g[4];
        int   v[4] = { m.x != 0, m.y != 0, m.z != 0, m.w != 0 };
        g[0] = v[0] ? fmaxf(t.x, b0) : b0;
        g[1] = v[1] ? fmaxf(t.y, b0) : b0;
        g[2] = v[2] ? fmaxf(t.z, b0) : b0;
        g[3] = v[3] ? fmaxf(t.w, b0) : b0;
        vc  += v[0] + v[1] + v[2] + v[3];
        inv |= !(v[0] & v[1] & v[2] & v[3]);

        // 4 interleaved binary searches: largest lo with sb[lo] <= g  (g >= b0 = sb[0])
        int lo[4] = {0, 0, 0, 0}, hi[4] = {DB - 1, DB - 1, DB - 1, DB - 1};
        #pragma unroll
        for (int it = 0; it < 7; ++it) {
            #pragma unroll
            for (int k = 0; k < 4; ++k) {
                int   mid = (lo[k] + hi[k] + 1) >> 1;
                bool  le  = (sb[mid] <= g[k]);
                lo[k] = le ? mid : lo[k];
                hi[k] = le ? hi[k] : mid - 1;
            }
        }

        #pragma unroll
        for (int k = 0; k < 4; ++k) {
            float d1 = g[k] - sb[lo[k]];                                   // >= 0; 0 for invalid
            float d2 = (lo[k] < DB - 1) ? (sb[lo[k] + 1] - g[k])
                                        : __int_as_float(INF_BITS);
            l1 += fminf(d1, d2);
            if (v[k]) {                    // valid points feed their bracketing segment
                unsigned gb = __float_as_uint(g[k]);   // positive: uint order == float order
                atomicMin(&smin[lo[k]], gb);
                atomicMax(&smax[lo[k]], gb);
            }
        }
    }
    if (inv) s_inv = 1;                    // benign race

    // Block-reduce loss1 + valid count
    #pragma unroll
    for (int o = 16; o; o >>= 1) {
        l1 += __shfl_down_sync(0xffffffffu, l1, o);
        vc += __shfl_down_sync(0xffffffffu, vc, o);
    }
    if ((tid & 31) == 0) { swl[tid >> 5] = l1; swc[tid >> 5] = vc; }
    __syncthreads();

    if (tid == 0) {
        float L = 0.0f; int C = 0;
        #pragma unroll
        for (int w = 0; w < TPB / 32; ++w) { L += swl[w]; C += swc[w]; }
        g_l1p[n * BPN + bx] = L;
        g_vcp[n * BPN + bx] = C;
        if (s_inv) {                       // all invalid points are g = b0 -> one segment-0 update
            unsigned bb = __float_as_uint(b0);
            atomicMin(&smin[0], bb);
            atomicMax(&smax[0], bb);
        }
    }
    __syncthreads();

    if (tid < DB) {
        g_psmin[(n * BPN + bx) * DB + tid] = __uint_as_float(smin[tid]);   // INF if empty
        g_psmax[(n * BPN + bx) * DB + tid] = __uint_as_float(smax[tid]);   // 0   if empty
    }
}

// One block per batch: merge 8 partials/segment, log-scan suffix-min / prefix-max,
// exact per-bin nearest-point distance, final sums.
__global__ void __launch_bounds__(DB) k_final(const float* __restrict__ bins,
                                              float* __restrict__ out) {
    __shared__ float suf[DB], pre[DB];
    __shared__ float redf[DB / 32];
    __shared__ int   redi[DB / 32];

    const int n = blockIdx.x, tid = threadIdx.x;
    const float INF = __int_as_float(INF_BITS);

    const float bj = bins[n * DB + tid];

    // Merge the 8 block-partials for this segment (coalesced across tid, MLP-batched)
    float mn = INF, mx = 0.0f;
    #pragma unroll
    for (int b = 0; b < BPN; ++b) {
        mn = fminf(mn, g_psmin[(n * BPN + b) * DB + tid]);
        mx = fmaxf(mx, g_psmax[(n * BPN + b) * DB + tid]);
    }

    // suffix-min over segments >= tid (inclusive), Hillis-Steele
    suf[tid] = mn;
    __syncthreads();
    #pragma unroll
    for (int o = 1; o < DB; o <<= 1) {
        float v = (tid + o < DB) ? suf[tid + o] : INF;
        __syncthreads();
        suf[tid] = fminf(suf[tid], v);
        __syncthreads();
    }

    // exclusive prefix-max over segments < tid:
    // seed with shifted smax, then inclusive max-scan
    pre[tid] = mx;
    __syncthreads();
    float seed = (tid > 0) ? pre[tid - 1] : 0.0f;
    __syncthreads();
    pre[tid] = seed;
    __syncthreads();
    #pragma unroll
    for (int o = 1; o < DB; o <<= 1) {
        float v = (tid >= o) ? pre[tid - o] : 0.0f;
        __syncthreads();
        pre[tid] = fmaxf(pre[tid], v);
        __syncthreads();
    }

    // nearest point >= bj lives in segments >= tid; nearest point < bj in segments < tid
    float up = suf[tid] - bj;                       // INF stays INF; else >= 0
    float pm = pre[tid];
    float dn = (pm > 0.0f) ? (bj - pm) : INF;       // 0 sentinel = no points below
    float l2 = fminf(up, dn);                       // exact min |g - bj| over all points

    // loss1 partials (8 per batch) + GLOBAL valid count (128 entries = one per thread)
    float l1 = (tid < BPN) ? g_l1p[n * BPN + tid] : 0.0f;
    int   vc = g_vcp[tid];                          // NB*BPN == DB exactly

    float acc = l1 + l2;
    #pragma unroll
    for (int o = 16; o; o >>= 1) {
        acc += __shfl_down_sync(0xffffffffu, acc, o);
        vc  += __shfl_down_sync(0xffffffffu, vc,  o);
    }
    if ((tid & 31) == 0) { redf[tid >> 5] = acc; redi[tid >> 5] = vc; }
    __syncthreads();

    if (tid == 0) {
        float s = 0.0f; int c = 0;
        #pragma unroll
        for (int w = 0; w < DB / 32; ++w) { s += redf[w]; c += redi[w]; }
        out[n] = s / (float)c;
    }
}

extern "C" void kernel_launch(void* const* d_in, const int* in_sizes, int n_in,
                              void* d_out, int out_size) {
    const float* bins = (const float*)d_in[0];
    const float* tdm  = (const float*)d_in[1];
    const int*   mask = (const int*)d_in[2];     // jnp.bool_ materialized as int32
    float*       out  = (float*)d_out;

    dim3 grid(BPN, NB);
    k_main<<<grid, TPB>>>(bins, tdm, mask);
    k_final<<<NB, DB>>>(bins, out);
}